// round 11
// baseline (speedup 1.0000x reference)
#include <cuda_runtime.h>
#include <math.h>

#define NB 16
#define NA 65536
#define NM 64
#define TPB 256
#define BINW 64.0f
#define NBINS 160          // anchor centers in [0, 10000) -> bin <= 156
#define KCAP 6             // per-bin candidate slots (3 x float4)
#define CAPB 512           // anchor slots per bin (mean 419, +4.5 sigma)
#define NSLOT (NBINS * CAPB)       // 81920
#define GRIDX2 (NSLOT / (TPB * 4)) // 80 blocks per image
#define NBLOCKS (NB * GRIDX2)      // 1280
#define GRID1 (NB + 64)            // 16 build blocks + 64 sort blocks

__device__ float g_ls[NBLOCKS];
__device__ int   g_np[NBLOCKS];
__device__ int   g_count = 0;

// Per-image bin tables (built once per call by blocks [0,16) of kernel 1).
__device__ float4 g_slist[NB * NBINS * 3];
__device__ int    g_scnt[NB * NBINS];
__device__ float2 g_sbox[NB * NM];

// Bin-sorted anchors (built by blocks [16,80) of kernel 1).
__device__ int    g_bcnt[NBINS];          // alloc counters; reset by kernel 2
__device__ float2 g_sa[NSLOT];
__device__ int    g_sidx[NSLOT];
__device__ int    g_overcnt = 0;          // overflow count; reset by kernel 2
__device__ float2 g_oa[NA];
__device__ int    g_oidx[NA];

// Tournament combine: take right if strictly better (cross-multiplied IoU
// compare, no division). Keep-left-on-tie + index-ordered pairing preserves
// the reference's first-maximum argmax semantics.
__device__ __forceinline__ void comb(float& iwl, float& sl, float& b0l, float& b1l,
                                     float iwr, float sr, float b0r, float b1r) {
    bool c = iwr * sl > iwl * sr;
    iwl = c ? iwr : iwl;
    sl  = c ? sr  : sl;
    b0l = c ? b0r : b0l;
    b1l = c ? b1r : b1l;
}

// Position of the (n+1)-th set bit of a 64-bit mask (n < popcll(m)).
__device__ __forceinline__ int nth_set_bit64(unsigned long long m, int n) {
    unsigned lo = (unsigned)m, hi = (unsigned)(m >> 32);
    int plo = __popc(lo);
    unsigned w = (n < plo) ? lo : hi;
    int base   = (n < plo) ? 0 : 32;
    int nn     = (n < plo) ? n : n - plo;
    return base + __fns(w, 0, nn + 1);
}

// ---- Kernel 1: blocks [0,16) build per-image tables; [16,80) sort anchors.
__global__ __launch_bounds__(TPB) void rl_prep_kernel(
    const float* __restrict__ anchors,  // (1, A, 2)
    const float* __restrict__ ann)      // (B, M, 3)
{
    const int tid = threadIdx.x;

    if (blockIdx.x < NB) {
        // ---------- Build per-image bin tables ----------
        const int b = blockIdx.x;
        // Boxes as (b0,b1). Invalid/pad -> sentinel (3e18,-3e18): iw,s ~ -6e18;
        // a real box beats a sentinel from either side of the cross-mult
        // compare, sentinels never beat real boxes, products stay finite.
        // Empty bin -> sentinel winner -> pos test false.
        __shared__ float2 sbox[NM];
        __shared__ unsigned long long smask[NBINS];

        if (tid < NM) {
            const float* a3 = ann + ((size_t)b * NM + tid) * 3;
            float b0 = a3[0], b1 = a3[1], lab = a3[2];
            bool valid = (lab != -1.0f);
            float2 v = valid ? make_float2(b0, b1) : make_float2(3e18f, -3e18f);
            sbox[tid] = v;
            g_sbox[b * NM + tid] = v;
        } else if (tid >= 64 && tid < 64 + NBINS) {
            smask[tid - 64] = 0ull;
        }
        __syncthreads();

        // Scatter: bin j accepts anchors with center in [64j, 64j+64); anchor
        // half-width <= 30 -> box relevant iff b1 > 64j-30 && b0 < 64j+94.
        if (tid < NM) {
            float2 bx = sbox[tid];
            if (bx.x < bx.y) {
                int jlo = (int)((bx.x - 94.0f) * (1.0f / BINW)) - 1;
                if (jlo < 0) jlo = 0;
                unsigned long long bit = 1ull << tid;
                for (int j = jlo; j < NBINS; j++) {
                    float base = (float)j * BINW;
                    if (base - 30.0f >= bx.y) break;
                    if (bx.x < base + 94.0f) atomicOr(&smask[j], bit);
                }
            }
        }
        __syncthreads();

        // Gather: ascending bit position = ascending box index -> first-max
        // argmax semantics preserved.
        for (int pair = tid; pair < NBINS * 3; pair += TPB) {
            int bin = pair / 3;
            int q   = pair - bin * 3;
            unsigned long long m = smask[bin];
            int pc = __popcll(m);
            int s0i = q * 2, s1i = q * 2 + 1;
            float2 v0 = make_float2(3e18f, -3e18f);
            float2 v1 = make_float2(3e18f, -3e18f);
            if (s0i < pc) v0 = sbox[nth_set_bit64(m, s0i)];
            if (s1i < pc) v1 = sbox[nth_set_bit64(m, s1i)];
            g_slist[b * NBINS * 3 + pair] = make_float4(v0.x, v0.y, v1.x, v1.y);
            if (q == 0) g_scnt[b * NBINS + bin] = pc;
        }
    } else {
        // ---------- Counting scatter of anchors into bin regions ----------
        // Order within a bin is irrelevant (anchors independent); each slot
        // carries its own (a0, a1, original index).
        const int blk = blockIdx.x - NB;         // 0..63
        const float2* anc2 = (const float2*)anchors;
        #pragma unroll
        for (int j = 0; j < 4; j++) {
            int a = blk * 1024 + j * TPB + tid;
            float2 av = anc2[a];
            int bin = (int)((0.5f * av.x + 0.5f * av.y) * (1.0f / BINW));
            int off = atomicAdd(&g_bcnt[bin], 1);
            if (off < CAPB) {
                g_sa[bin * CAPB + off]   = av;
                g_sidx[bin * CAPB + off] = a;
            } else {   // statistically ~never; correctness fallback
                int o = atomicAdd(&g_overcnt, 1);
                g_oa[o]   = av;
                g_oidx[o] = a;
            }
        }
    }
}

// Process one anchor against image-b tables. Returns via lsum/lpos.
__device__ __forceinline__ void process_anchor(
    float2 av, int aidx,
    const float4* __restrict__ sl4, const int* __restrict__ scnt,
    const float2* __restrict__ sbxg, const float2* __restrict__ reg2,
    float& lsum, int& lpos)
{
    const float a0 = av.x, a1 = av.y;
    const float aw   = a1 - a0;
    const float actr = 0.5f * a0 + 0.5f * a1;
    const int bin = (int)(actr * (1.0f / BINW));
    const int cnt = __ldg(&scnt[bin]);

    // Cross-multiplied running argmax (no division): iou_i > iou_j <=>
    // iw_i*s_j > iw_j*s_i, s = aw+area > 0 for real boxes. Strict '>' in
    // ascending index order = first maximum.
    float iw0, s0, bb0, bb1;
    if (cnt <= KCAP) {
        float4 q0 = __ldg(&sl4[bin * 3 + 0]);   // warp-broadcast (uniform bin)
        float4 q1 = __ldg(&sl4[bin * 3 + 1]);
        float4 q2 = __ldg(&sl4[bin * 3 + 2]);

        float iwA = fminf(a1, q0.y) - fmaxf(a0, q0.x), sA = aw + (q0.y - q0.x);
        float iwB = fminf(a1, q0.w) - fmaxf(a0, q0.z), sB = aw + (q0.w - q0.z);
        float iwC = fminf(a1, q1.y) - fmaxf(a0, q1.x), sC = aw + (q1.y - q1.x);
        float iwD = fminf(a1, q1.w) - fmaxf(a0, q1.z), sD = aw + (q1.w - q1.z);
        float iwE = fminf(a1, q2.y) - fmaxf(a0, q2.x), sE = aw + (q2.y - q2.x);
        float iwF = fminf(a1, q2.w) - fmaxf(a0, q2.z), sF = aw + (q2.w - q2.z);

        float b0A = q0.x, b1A = q0.y;
        float b0C = q1.x, b1C = q1.y;
        float b0E = q2.x, b1E = q2.y;
        comb(iwA, sA, b0A, b1A, iwB, sB, q0.z, q0.w);
        comb(iwC, sC, b0C, b1C, iwD, sD, q1.z, q1.w);
        comb(iwE, sE, b0E, b1E, iwF, sF, q2.z, q2.w);
        comb(iwA, sA, b0A, b1A, iwC, sC, b0C, b1C);
        comb(iwA, sA, b0A, b1A, iwE, sE, b0E, b1E);
        iw0 = iwA; s0 = sA; bb0 = b0A; bb1 = b1A;
    } else {  // overflow fallback (P ~ 1e-4 per bin): full scan, correct
        iw0 = 0.0f; s0 = 1.0f; bb0 = 0.0f; bb1 = 0.0f;
        #pragma unroll 8
        for (int k = 0; k < NM; k++) {
            float2 bx = __ldg(&sbxg[k]);
            float s  = aw + (bx.y - bx.x);
            float iw = fminf(a1, bx.y) - fmaxf(a0, bx.x);
            if (iw * s0 > iw0 * s) {
                iw0 = iw; s0 = s; bb0 = bx.x; bb1 = bx.y;
            }
        }
    }

    // pos: iou >= 0.5 <=> 3*iw >= s (exact under the 1e-8 clamp for iw > 0;
    // false for iw <= 0 and sentinel winners). With bin-sorted anchors the
    // pos lanes cluster, so ~94% of warps skip the whole epilogue INCLUDING
    // the regressions gather (asm volatile -> cannot be hoisted).
    if (3.0f * iw0 >= s0) {
        lpos++;
        float rx, ry;
        asm volatile("ld.global.nc.v2.f32 {%0, %1}, [%2];"
                     : "=f"(rx), "=f"(ry) : "l"(reg2 + aidx) : "memory");

        float gwr  = bb1 - bb0;
        float gctr = bb0 + 0.5f * gwr;
        float gw   = fmaxf(gwr, 1.0f);

        // fast-math: ~1e-7 rel err vs 1e-3 threshold (measured 0.0 R3-R10)
        float tdx = __fdividef(gctr - actr, aw) * 10.0f;
        float tdw = __logf(__fdividef(gw, aw)) * 5.0f;

        float d0 = fabsf(tdx - rx);
        float d1 = fabsf(tdw - ry);
        const float third = 1.0f / 9.0f;
        lsum += (d0 <= third) ? 4.5f * d0 * d0 : d0 - (0.5f / 9.0f);
        lsum += (d1 <= third) ? 4.5f * d1 * d1 : d1 - (0.5f / 9.0f);
    }
}

// ---- Kernel 2: warp-uniform hot loop over bin-sorted anchor slots. ----
__global__ __launch_bounds__(TPB) void rl_main_kernel(
    const float* __restrict__ reg,      // (B, A, 2)
    float* __restrict__ out)
{
    const int b   = blockIdx.y;
    const int tid = threadIdx.x;

    float lsum = 0.0f;
    int   lpos = 0;

    const float2* reg2 = (const float2*)(reg + (size_t)b * NA * 2);
    const float4* sl4  = g_slist + b * NBINS * 3;
    const int*    scnt = g_scnt  + b * NBINS;
    const float2* sbxg = g_sbox  + b * NM;
    const int abase = blockIdx.x * TPB + tid;

    #pragma unroll
    for (int j = 0; j < 4; j++) {
        const int s   = abase + j * (GRIDX2 * TPB);   // 0..81919
        const int bin = s >> 9;                        // CAPB = 512
        const int pib = s & (CAPB - 1);
        int bc = __ldg(&g_bcnt[bin]);                  // warp-uniform
        if (pib < min(bc, CAPB)) {
            float2 av = g_sa[s];                       // coalesced
            int  aidx = g_sidx[s];                     // coalesced
            process_anchor(av, aidx, sl4, scnt, sbxg, reg2, lsum, lpos);
        }
    }

    // Overflow anchors (normally zero): one block per image handles them.
    if (blockIdx.x == 0) {
        int oc = __ldcg(&g_overcnt);
        for (int i = tid; i < oc; i += TPB)
            process_anchor(g_oa[i], g_oidx[i], sl4, scnt, sbxg, reg2, lsum, lpos);
    }

    // Block reduction (8 warps)
    #pragma unroll
    for (int off = 16; off > 0; off >>= 1) {
        lsum += __shfl_down_sync(0xFFFFFFFFu, lsum, off);
        lpos += __shfl_down_sync(0xFFFFFFFFu, lpos, off);
    }
    __shared__ float wsum[TPB / 32];
    __shared__ int   wpos[TPB / 32];
    __shared__ int   slast;
    int wid = tid >> 5, lane = tid & 31;
    if (lane == 0) { wsum[wid] = lsum; wpos[wid] = lpos; }
    __syncthreads();

    if (tid == 0) {
        float s = 0.0f; int p = 0;
        #pragma unroll
        for (int i = 0; i < TPB / 32; i++) { s += wsum[i]; p += wpos[i]; }
        int slot = b * GRIDX2 + blockIdx.x;
        g_ls[slot] = s;
        g_np[slot] = p;
        __threadfence();
        int c = atomicAdd(&g_count, 1);
        slast = (c == NBLOCKS - 1) ? 1 : 0;
    }
    __syncthreads();
    if (!slast) return;

    // ---- Last block: reset counters (replay-safe) + final reduce. ----
    if (tid == 0)  g_count = 0;
    if (tid == 1)  g_overcnt = 0;
    if (tid < NBINS) g_bcnt[tid] = 0;   // all other blocks already finished

    int bb = tid >> 4;           // image 0..15
    int j  = tid & 15;
    float s = 0.0f; int p = 0;
    #pragma unroll
    for (int k = 0; k < 5; k++) {        // 80 partials = 16 lanes x 5
        s += __ldcg(&g_ls[bb * GRIDX2 + j + k * 16]);
        p += __ldcg(&g_np[bb * GRIDX2 + j + k * 16]);
    }
    #pragma unroll
    for (int off = 8; off > 0; off >>= 1) {
        s += __shfl_down_sync(0xFFFFFFFFu, s, off, 16);
        p += __shfl_down_sync(0xFFFFFFFFu, p, off, 16);
    }
    __shared__ float simg[NB];
    if (j == 0) {
        // npos > 0 implies a valid box exists, so valid.any() is subsumed.
        simg[bb] = (p > 0) ? s / (2.0f * (float)p) : 0.0f;
    }
    __syncthreads();
    if (tid < 32) {
        float l = (tid < NB) ? simg[tid] : 0.0f;
        #pragma unroll
        for (int off = 16; off > 0; off >>= 1)
            l += __shfl_down_sync(0xFFFFFFFFu, l, off);
        if (tid == 0) out[0] = l / (float)NB;
    }
}

extern "C" void kernel_launch(void* const* d_in, const int* in_sizes, int n_in,
                              void* d_out, int out_size) {
    const float* reg     = (const float*)d_in[0];  // (16, 65536, 2)
    const float* anchors = (const float*)d_in[1];  // (1, 65536, 2)
    const float* ann     = (const float*)d_in[2];  // (16, 64, 3)
    float* out = (float*)d_out;

    rl_prep_kernel<<<GRID1, TPB>>>(anchors, ann);
    dim3 grid(GRIDX2, NB);
    rl_main_kernel<<<grid, TPB>>>(reg, out);
}

// round 12
// speedup vs baseline: 1.2603x; 1.2603x over previous
#include <cuda_runtime.h>
#include <math.h>

#define NB 16
#define NA 65536
#define NM 64
#define TPB 256
#define GRIDX 16
#define NBLOCKS (NB * GRIDX)     // 256
#define NITER (NA / (GRIDX * TPB))  // 16 anchors per thread
#define BINW 64.0f
#define NBINS 160     // anchor centers in [0, 10000) -> bin <= 156
#define KCAP 6        // fixed per-bin slots (3 x float4); overflow -> full scan

__device__ float g_ls[NBLOCKS];
__device__ int   g_np[NBLOCKS];
__device__ int   g_count = 0;

// Tournament combine: take right if strictly better (cross-multiplied IoU
// compare, no division). Keep-left-on-tie + index-ordered pairing preserves
// the reference's first-maximum argmax semantics.
__device__ __forceinline__ void comb(float& iwl, float& sl, float& b0l, float& b1l,
                                     float iwr, float sr, float b0r, float b1r) {
    bool c = iwr * sl > iwl * sr;
    iwl = c ? iwr : iwl;
    sl  = c ? sr  : sl;
    b0l = c ? b0r : b0l;
    b1l = c ? b1r : b1l;
}

// Position of the (n+1)-th set bit of a 64-bit mask (n < popcll(m)).
__device__ __forceinline__ int nth_set_bit64(unsigned long long m, int n) {
    unsigned lo = (unsigned)m, hi = (unsigned)(m >> 32);
    int plo = __popc(lo);
    unsigned w = (n < plo) ? lo : hi;
    int base   = (n < plo) ? 0 : 32;
    int nn     = (n < plo) ? n : n - plo;
    return base + __fns(w, 0, nn + 1);
}

__global__ __launch_bounds__(TPB) void rl_kernel(
    const float* __restrict__ reg,      // (B, A, 2)
    const float* __restrict__ anchors,  // (1, A, 2)
    const float* __restrict__ ann,      // (B, M, 3)
    float* __restrict__ out)
{
    const int b   = blockIdx.y;
    const int tid = threadIdx.x;

    // Boxes as (b0, b1). Invalid/pad -> sentinel (3e18, -3e18): iw ~ -6e18,
    // s ~ -6e18; a real box beats a sentinel from either side of the
    // cross-mult compare, sentinels never win over real boxes, all products
    // stay finite. Empty bin -> sentinel winner -> pos test false.
    __shared__ float2 sbox[NM];
    __shared__ unsigned long long smask[NBINS];
    __shared__ float2 slist[NBINS * KCAP];   // 48B per bin, 16B-aligned groups
    __shared__ int    scnt[NBINS];

    // Region 1: load boxes (tid<64) in parallel with zeroing masks.
    if (tid < NM) {
        const float* a3 = ann + ((size_t)b * NM + tid) * 3;
        float b0 = a3[0], b1 = a3[1], lab = a3[2];
        bool valid = (lab != -1.0f);
        sbox[tid] = valid ? make_float2(b0, b1) : make_float2(3e18f, -3e18f);
    } else if (tid >= 64 && tid < 64 + NBINS) {
        smask[tid - 64] = 0ull;
    }
    __syncthreads();

    // Region 2: scatter — one thread per box marks the <=4 bins it can
    // influence. Bin j accepts anchors with center in [j*64,(j+1)*64);
    // anchor half-width <= 30, so a box overlaps such an anchor only if
    //   b1 > j*64 - 30  &&  b0 < j*64 + 94.
    if (tid < NM) {
        float2 bx = sbox[tid];
        if (bx.x < bx.y) {   // real box
            int jlo = (int)((bx.x - 94.0f) * (1.0f / BINW)) - 1;
            if (jlo < 0) jlo = 0;
            unsigned long long bit = 1ull << tid;
            for (int j = jlo; j < NBINS; j++) {
                float base = (float)j * BINW;
                if (base - 30.0f >= bx.y) break;
                if (bx.x < base + 94.0f)
                    atomicOr(&smask[j], bit);
            }
        }
    }
    __syncthreads();

    // Region 3: gather — fully parallel over (bin, slot) pairs. Ascending
    // bit position = ascending box index -> first-max argmax preserved.
    #pragma unroll
    for (int pair = tid; pair < NBINS * KCAP; pair += TPB) {
        int bin  = pair / KCAP;
        int slot = pair - bin * KCAP;
        unsigned long long m = smask[bin];
        int pc = __popcll(m);
        float2 v = make_float2(3e18f, -3e18f);
        if (slot < pc && slot < KCAP)
            v = sbox[nth_set_bit64(m, slot)];
        slist[pair] = v;
        if (slot == 0) scnt[bin] = pc;
    }
    __syncthreads();

    float lsum = 0.0f;
    int   lpos = 0;

    const float2* anc2 = (const float2*)anchors;
    const float2* reg2 = (const float2*)(reg + (size_t)b * NA * 2);
    const float4* sl4  = (const float4*)slist;
    const int abase = blockIdx.x * TPB + tid;

    // 16 independent anchor iterations per thread: deep unroll window for
    // load batching and latency amortization (the one knob R2-R11 never
    // varied — every prior round used exactly 4).
    #pragma unroll
    for (int j = 0; j < NITER; j++) {
        const int a = abase + j * (GRIDX * TPB);
        float2 av = anc2[a];
        float2 r  = reg2[a];          // unconditional: coalesced, MLP
        const float a0 = av.x, a1 = av.y;
        const float aw   = a1 - a0;
        const float actr = 0.5f * a0 + 0.5f * a1;

        const int bin = (int)(actr * (1.0f / BINW));   // 0..156
        const int cnt = scnt[bin];

        float iw0, s0, bb0, bb1;
        if (cnt <= KCAP) {
            // 3 independent LDS.128 -> 6 candidate boxes
            float4 q0 = sl4[bin * 3 + 0];
            float4 q1 = sl4[bin * 3 + 1];
            float4 q2 = sl4[bin * 3 + 2];

            float iwA = fminf(a1, q0.y) - fmaxf(a0, q0.x), sA = aw + (q0.y - q0.x);
            float iwB = fminf(a1, q0.w) - fmaxf(a0, q0.z), sB = aw + (q0.w - q0.z);
            float iwC = fminf(a1, q1.y) - fmaxf(a0, q1.x), sC = aw + (q1.y - q1.x);
            float iwD = fminf(a1, q1.w) - fmaxf(a0, q1.z), sD = aw + (q1.w - q1.z);
            float iwE = fminf(a1, q2.y) - fmaxf(a0, q2.x), sE = aw + (q2.y - q2.x);
            float iwF = fminf(a1, q2.w) - fmaxf(a0, q2.z), sF = aw + (q2.w - q2.z);

            // tournament: 3 independent combines, then 2 (depth 3)
            float b0A = q0.x, b1A = q0.y;
            float b0C = q1.x, b1C = q1.y;
            float b0E = q2.x, b1E = q2.y;
            comb(iwA, sA, b0A, b1A, iwB, sB, q0.z, q0.w);
            comb(iwC, sC, b0C, b1C, iwD, sD, q1.z, q1.w);
            comb(iwE, sE, b0E, b1E, iwF, sF, q2.z, q2.w);
            comb(iwA, sA, b0A, b1A, iwC, sC, b0C, b1C);
            comb(iwA, sA, b0A, b1A, iwE, sE, b0E, b1E);
            iw0 = iwA; s0 = sA; bb0 = b0A; bb1 = b1A;
        } else {  // overflow fallback (P ~ 1e-4 per bin): full scan, correct
            iw0 = 0.0f; s0 = 1.0f; bb0 = 0.0f; bb1 = 0.0f;
            #pragma unroll 8
            for (int k = 0; k < NM; k++) {
                float2 bx = sbox[k];
                float s  = aw + (bx.y - bx.x);
                float iw = fminf(a1, bx.y) - fmaxf(a0, bx.x);
                if (iw * s0 > iw0 * s) {
                    iw0 = iw; s0 = s; bb0 = bx.x; bb1 = bx.y;
                }
            }
        }

        // pos: iou >= 0.5  <=>  3*iw >= s  (exact under the 1e-8 clamp for
        // iw > 0; false for iw <= 0 and for sentinel winners)
        if (3.0f * iw0 >= s0) {
            lpos++;
            float gwr  = bb1 - bb0;
            float gctr = bb0 + 0.5f * gwr;
            float gw   = fmaxf(gwr, 1.0f);

            // fast-math: ~1e-7 rel err vs 1e-3 threshold (measured 0.0 R3-R11)
            float tdx = __fdividef(gctr - actr, aw) * 10.0f;
            float tdw = __logf(__fdividef(gw, aw)) * 5.0f;

            float d0 = fabsf(tdx - r.x);
            float d1 = fabsf(tdw - r.y);
            const float third = 1.0f / 9.0f;
            lsum += (d0 <= third) ? 4.5f * d0 * d0 : d0 - (0.5f / 9.0f);
            lsum += (d1 <= third) ? 4.5f * d1 * d1 : d1 - (0.5f / 9.0f);
        }
    }

    // Block reduction (8 warps)
    #pragma unroll
    for (int off = 16; off > 0; off >>= 1) {
        lsum += __shfl_down_sync(0xFFFFFFFFu, lsum, off);
        lpos += __shfl_down_sync(0xFFFFFFFFu, lpos, off);
    }
    __shared__ float wsum[TPB / 32];
    __shared__ int   wpos[TPB / 32];
    __shared__ int   slast;
    int wid = tid >> 5, lane = tid & 31;
    if (lane == 0) { wsum[wid] = lsum; wpos[wid] = lpos; }
    __syncthreads();

    if (tid == 0) {
        float s = 0.0f; int p = 0;
        #pragma unroll
        for (int i = 0; i < TPB / 32; i++) { s += wsum[i]; p += wpos[i]; }
        int slot = b * GRIDX + blockIdx.x;
        g_ls[slot] = s;
        g_np[slot] = p;
        __threadfence();
        int c = atomicAdd(&g_count, 1);
        slast = (c == NBLOCKS - 1) ? 1 : 0;
    }
    __syncthreads();
    if (!slast) return;

    // ---- Last block: reduce 256 partials (one per thread) + write out. ----
    if (tid == 0) g_count = 0;   // replay-safe reset

    // tid = image*16 + part  (GRIDX == 16)
    float s = __ldcg(&g_ls[tid]);
    int   p = __ldcg(&g_np[tid]);
    #pragma unroll
    for (int off = 8; off > 0; off >>= 1) {
        s += __shfl_down_sync(0xFFFFFFFFu, s, off, 16);
        p += __shfl_down_sync(0xFFFFFFFFu, p, off, 16);
    }
    __shared__ float simg[NB];
    if ((tid & 15) == 0) {
        // npos > 0 implies a valid box exists, so valid.any() is subsumed.
        simg[tid >> 4] = (p > 0) ? s / (2.0f * (float)p) : 0.0f;
    }
    __syncthreads();
    if (tid < 32) {
        float l = (tid < NB) ? simg[tid] : 0.0f;
        #pragma unroll
        for (int off = 16; off > 0; off >>= 1)
            l += __shfl_down_sync(0xFFFFFFFFu, l, off);
        if (tid == 0) out[0] = l / (float)NB;
    }
}

extern "C" void kernel_launch(void* const* d_in, const int* in_sizes, int n_in,
                              void* d_out, int out_size) {
    const float* reg     = (const float*)d_in[0];  // (16, 65536, 2)
    const float* anchors = (const float*)d_in[1];  // (1, 65536, 2)
    const float* ann     = (const float*)d_in[2];  // (16, 64, 3)
    float* out = (float*)d_out;

    dim3 grid(GRIDX, NB);
    rl_kernel<<<grid, TPB>>>(reg, anchors, ann, out);
}

// round 13
// speedup vs baseline: 1.5726x; 1.2479x over previous
#include <cuda_runtime.h>
#include <math.h>

#define NB 16
#define NA 65536
#define NM 64
#define TPB 256
#define GRIDX 64
#define NBLOCKS (NB * GRIDX)     // 1024
#define NITER (NA / (GRIDX * TPB * 2))   // 2 float4 iters = 4 anchors/thread
#define BINW 64.0f
#define NBINS 160     // anchor centers in [0, 10000) -> bin <= 156
#define KCAP 6        // fixed per-bin slots (3 x float4); overflow -> full scan

__device__ float g_ls[NBLOCKS];
__device__ int   g_np[NBLOCKS];
__device__ int   g_count = 0;

// Position of the (n+1)-th set bit of a 64-bit mask (n < popcll(m)).
__device__ __forceinline__ int nth_set_bit64(unsigned long long m, int n) {
    unsigned lo = (unsigned)m, hi = (unsigned)(m >> 32);
    int plo = __popc(lo);
    unsigned w = (n < plo) ? lo : hi;
    int base   = (n < plo) ? 0 : 32;
    int nn     = (n < plo) ? n : n - plo;
    return base + __fns(w, 0, nn + 1);
}

// Smooth-L1 epilogue for a pos anchor. fast-math intrinsics: ~1e-7 rel err
// vs the 1e-3 threshold (measured rel_err 0.0 across R3-R12).
__device__ __forceinline__ void epilogue(float bb0, float bb1, float actr,
                                         float aw, float rx, float ry,
                                         float& lsum) {
    float gwr  = bb1 - bb0;
    float gctr = bb0 + 0.5f * gwr;
    float gw   = fmaxf(gwr, 1.0f);
    float tdx = __fdividef(gctr - actr, aw) * 10.0f;
    float tdw = __logf(__fdividef(gw, aw)) * 5.0f;
    float d0 = fabsf(tdx - rx);
    float d1 = fabsf(tdw - ry);
    const float third = 1.0f / 9.0f;
    lsum += (d0 <= third) ? 4.5f * d0 * d0 : d0 - (0.5f / 9.0f);
    lsum += (d1 <= third) ? 4.5f * d1 * d1 : d1 - (0.5f / 9.0f);
}

// One anchor vs its bin's 6 candidate slots (slot-tracking tournament) with
// rare full-scan fallback. Cross-multiplied compare (no division):
// iou_i > iou_j <=> iw_i*s_j > iw_j*s_i, s = aw + area > 0 for real boxes.
// Strict '>' with ascending-index pairing keeps the FIRST maximum, matching
// the reference argmax. Sentinel slots (3e18,-3e18) give iw,s ~ -6e18 and
// can never beat a real box from either side; products stay finite.
__device__ __forceinline__ void process_anchor(
    float a0, float a1, float rx, float ry,
    const float4* __restrict__ sl4, const float2* __restrict__ sl2,
    const int* __restrict__ scnt, const float2* __restrict__ sbox,
    float& lsum, int& lpos)
{
    const float aw   = a1 - a0;
    const float actr = 0.5f * a0 + 0.5f * a1;
    const int bin = (int)(actr * (1.0f / BINW));   // 0..156
    const int cnt = scnt[bin];

    if (cnt <= KCAP) {
        float4 q0 = sl4[bin * 3 + 0];
        float4 q1 = sl4[bin * 3 + 1];
        float4 q2 = sl4[bin * 3 + 2];

        float iwA = fminf(a1, q0.y) - fmaxf(a0, q0.x), sA = aw + (q0.y - q0.x);
        float iwB = fminf(a1, q0.w) - fmaxf(a0, q0.z), sB = aw + (q0.w - q0.z);
        float iwC = fminf(a1, q1.y) - fmaxf(a0, q1.x), sC = aw + (q1.y - q1.x);
        float iwD = fminf(a1, q1.w) - fmaxf(a0, q1.z), sD = aw + (q1.w - q1.z);
        float iwE = fminf(a1, q2.y) - fmaxf(a0, q2.x), sE = aw + (q2.y - q2.x);
        float iwF = fminf(a1, q2.w) - fmaxf(a0, q2.z), sF = aw + (q2.w - q2.z);

        // 3 independent pair-combines, then 2 (depth 3), tracking slot ids.
        bool cAB = iwB * sA > iwA * sB;
        float iw0 = cAB ? iwB : iwA, s0 = cAB ? sB : sA; int k0 = cAB ? 1 : 0;
        bool cCD = iwD * sC > iwC * sD;
        float iw1 = cCD ? iwD : iwC, s1 = cCD ? sD : sC; int k1 = cCD ? 3 : 2;
        bool cEF = iwF * sE > iwE * sF;
        float iw2 = cEF ? iwF : iwE, s2 = cEF ? sF : sE; int k2 = cEF ? 5 : 4;
        bool c01 = iw1 * s0 > iw0 * s1;
        iw0 = c01 ? iw1 : iw0; s0 = c01 ? s1 : s0; k0 = c01 ? k1 : k0;
        bool c02 = iw2 * s0 > iw0 * s2;
        iw0 = c02 ? iw2 : iw0; s0 = c02 ? s2 : s0; k0 = c02 ? k2 : k0;

        // pos: iou >= 0.5 <=> 3*iw >= s (exact under the 1e-8 clamp for
        // iw > 0; false for iw <= 0 and sentinel winners). Winner coords
        // fetched only here (~6% of lanes).
        if (3.0f * iw0 >= s0) {
            lpos++;
            float2 wb = sl2[bin * KCAP + k0];
            epilogue(wb.x, wb.y, actr, aw, rx, ry, lsum);
        }
    } else {  // overflow fallback (P ~ 1e-4 per bin): full scan, correct
        float iw0 = 0.0f, s0 = 1.0f, bb0 = 0.0f, bb1 = 0.0f;
        #pragma unroll 8
        for (int k = 0; k < NM; k++) {
            float2 bx = sbox[k];
            float s  = aw + (bx.y - bx.x);
            float iw = fminf(a1, bx.y) - fmaxf(a0, bx.x);
            if (iw * s0 > iw0 * s) {
                iw0 = iw; s0 = s; bb0 = bx.x; bb1 = bx.y;
            }
        }
        if (3.0f * iw0 >= s0) {
            lpos++;
            epilogue(bb0, bb1, actr, aw, rx, ry, lsum);
        }
    }
}

__global__ __launch_bounds__(TPB) void rl_kernel(
    const float* __restrict__ reg,      // (B, A, 2)
    const float* __restrict__ anchors,  // (1, A, 2)
    const float* __restrict__ ann,      // (B, M, 3)
    float* __restrict__ out)
{
    const int b   = blockIdx.y;
    const int tid = threadIdx.x;

    __shared__ float2 sbox[NM];
    __shared__ unsigned long long smask[NBINS];
    __shared__ float2 slist[NBINS * KCAP];   // 48B per bin, 16B-aligned groups
    __shared__ int    scnt[NBINS];

    // Region 1: load boxes (tid<64) in parallel with zeroing masks.
    // Invalid/pad boxes -> sentinel (3e18, -3e18).
    if (tid < NM) {
        const float* a3 = ann + ((size_t)b * NM + tid) * 3;
        float b0 = a3[0], b1 = a3[1], lab = a3[2];
        bool valid = (lab != -1.0f);
        sbox[tid] = valid ? make_float2(b0, b1) : make_float2(3e18f, -3e18f);
    } else if (tid >= 64 && tid < 64 + NBINS) {
        smask[tid - 64] = 0ull;
    }
    __syncthreads();

    // Region 2: scatter — one thread per box marks the <=4 bins it can
    // influence. Bin j accepts anchors with center in [j*64,(j+1)*64);
    // anchor half-width <= 30, so a box overlaps such an anchor only if
    //   b1 > j*64 - 30  &&  b0 < j*64 + 94.
    if (tid < NM) {
        float2 bx = sbox[tid];
        if (bx.x < bx.y) {   // real box
            int jlo = (int)((bx.x - 94.0f) * (1.0f / BINW)) - 1;
            if (jlo < 0) jlo = 0;
            unsigned long long bit = 1ull << tid;
            for (int j = jlo; j < NBINS; j++) {
                float base = (float)j * BINW;
                if (base - 30.0f >= bx.y) break;
                if (bx.x < base + 94.0f)
                    atomicOr(&smask[j], bit);
            }
        }
    }
    __syncthreads();

    // Region 3: gather — fully parallel over (bin, slot) pairs. Ascending
    // bit position = ascending box index -> first-max argmax preserved.
    #pragma unroll
    for (int pair = tid; pair < NBINS * KCAP; pair += TPB) {
        int bin  = pair / KCAP;
        int slot = pair - bin * KCAP;
        unsigned long long m = smask[bin];
        int pc = __popcll(m);
        float2 v = make_float2(3e18f, -3e18f);
        if (slot < pc && slot < KCAP)
            v = sbox[nth_set_bit64(m, slot)];
        slist[pair] = v;
        if (slot == 0) scnt[bin] = pc;
    }
    __syncthreads();

    float lsum = 0.0f;
    int   lpos = 0;

    const float4* anc4 = (const float4*)anchors;            // 2 anchors / ld
    const float4* reg4 = (const float4*)(reg + (size_t)b * NA * 2);
    const float4* sl4  = (const float4*)slist;
    const float2* sl2  = (const float2*)slist;
    const int pbase = blockIdx.x * TPB + tid;                // pair index

    #pragma unroll
    for (int j = 0; j < NITER; j++) {
        const int p = pbase + j * (GRIDX * TPB);   // 0..32767
        float4 av = anc4[p];   // anchors 2p, 2p+1
        float4 rv = reg4[p];
        process_anchor(av.x, av.y, rv.x, rv.y, sl4, sl2, scnt, sbox, lsum, lpos);
        process_anchor(av.z, av.w, rv.z, rv.w, sl4, sl2, scnt, sbox, lsum, lpos);
    }

    // Block reduction (8 warps)
    #pragma unroll
    for (int off = 16; off > 0; off >>= 1) {
        lsum += __shfl_down_sync(0xFFFFFFFFu, lsum, off);
        lpos += __shfl_down_sync(0xFFFFFFFFu, lpos, off);
    }
    __shared__ float wsum[TPB / 32];
    __shared__ int   wpos[TPB / 32];
    __shared__ int   slast;
    int wid = tid >> 5, lane = tid & 31;
    if (lane == 0) { wsum[wid] = lsum; wpos[wid] = lpos; }
    __syncthreads();

    if (tid == 0) {
        float s = 0.0f; int p = 0;
        #pragma unroll
        for (int i = 0; i < TPB / 32; i++) { s += wsum[i]; p += wpos[i]; }
        int slot = b * GRIDX + blockIdx.x;
        g_ls[slot] = s;
        g_np[slot] = p;
        __threadfence();
        int c = atomicAdd(&g_count, 1);
        slast = (c == NBLOCKS - 1) ? 1 : 0;
    }
    __syncthreads();
    if (!slast) return;

    // ---- Last block: reduce 1024 partials and write the scalar. ----
    if (tid == 0) g_count = 0;   // replay-safe reset

    int bb = tid >> 4;           // image 0..15
    int j  = tid & 15;
    float s = __ldcg(&g_ls[bb * GRIDX + j])
            + __ldcg(&g_ls[bb * GRIDX + j + 16])
            + __ldcg(&g_ls[bb * GRIDX + j + 32])
            + __ldcg(&g_ls[bb * GRIDX + j + 48]);
    int   p = __ldcg(&g_np[bb * GRIDX + j])
            + __ldcg(&g_np[bb * GRIDX + j + 16])
            + __ldcg(&g_np[bb * GRIDX + j + 32])
            + __ldcg(&g_np[bb * GRIDX + j + 48]);
    #pragma unroll
    for (int off = 8; off > 0; off >>= 1) {
        s += __shfl_down_sync(0xFFFFFFFFu, s, off, 16);
        p += __shfl_down_sync(0xFFFFFFFFu, p, off, 16);
    }
    __shared__ float simg[NB];
    if (j == 0) {
        // npos > 0 implies a valid box exists, so valid.any() is subsumed.
        simg[bb] = (p > 0) ? s / (2.0f * (float)p) : 0.0f;
    }
    __syncthreads();
    if (tid < 32) {
        float l = (tid < NB) ? simg[tid] : 0.0f;
        #pragma unroll
        for (int off = 16; off > 0; off >>= 1)
            l += __shfl_down_sync(0xFFFFFFFFu, l, off);
        if (tid == 0) out[0] = l / (float)NB;
    }
}

extern "C" void kernel_launch(void* const* d_in, const int* in_sizes, int n_in,
                              void* d_out, int out_size) {
    const float* reg     = (const float*)d_in[0];  // (16, 65536, 2)
    const float* anchors = (const float*)d_in[1];  // (1, 65536, 2)
    const float* ann     = (const float*)d_in[2];  // (16, 64, 3)
    float* out = (float*)d_out;

    dim3 grid(GRIDX, NB);
    rl_kernel<<<grid, TPB>>>(reg, anchors, ann, out);
}